// round 4
// baseline (speedup 1.0000x reference)
#include <cuda_runtime.h>
#include <cuda_fp16.h>
#include <cstdint>
#include <cstddef>

// Problem constants
static constexpr int BB = 2, NN = 65536, CC = 256, HH = 8, DD = 64, SS = 64;
static constexpr int MROWS = BB * NN;          // 131072
static constexpr int SPLITS = 64;              // token splits per (b,h) in stage 2
static constexpr int TOK_PER_SPLIT = NN / SPLITS;  // 1024
static constexpr int TILE_T = 64;
static constexpr int TILES = TOK_PER_SPLIT / TILE_T;  // 16

// ---------------- device scratch (no allocation allowed) ----------------
__device__ __half g_Wb[256 * 1024];          // [K=256][N=1024] fp16
__device__ float  g_bias[1024];
__device__ __half g_Wsb[64 * 64];            // W_slice [d][s]
__device__ float  g_bslice[64];
__device__ float  g_invtemp[8];
__device__ __half g_PF[(size_t)MROWS * 1024];     // 256 MB
__device__ float  g_PartT[16 * SPLITS * 64 * 64]; // 16.8 MB partials
__device__ float  g_PartN[16 * SPLITS * 64];

// ---------------- mma helpers ----------------
__device__ __forceinline__ uint32_t smem_u32(const void* p) {
    return (uint32_t)__cvta_generic_to_shared(p);
}
__device__ __forceinline__ void ldm_x4(uint32_t* r, uint32_t addr) {
    asm volatile("ldmatrix.sync.aligned.m8n8.x4.shared.b16 {%0,%1,%2,%3}, [%4];"
                 : "=r"(r[0]), "=r"(r[1]), "=r"(r[2]), "=r"(r[3]) : "r"(addr));
}
__device__ __forceinline__ void ldm_x4_t(uint32_t* r, uint32_t addr) {
    asm volatile("ldmatrix.sync.aligned.m8n8.x4.trans.shared.b16 {%0,%1,%2,%3}, [%4];"
                 : "=r"(r[0]), "=r"(r[1]), "=r"(r[2]), "=r"(r[3]) : "r"(addr));
}
__device__ __forceinline__ void mma_f16(float* c, const uint32_t* a, uint32_t b0, uint32_t b1) {
    asm volatile("mma.sync.aligned.m16n8k16.row.col.f32.f16.f16.f32 "
                 "{%0,%1,%2,%3}, {%4,%5,%6,%7}, {%8,%9}, {%0,%1,%2,%3};"
                 : "+f"(c[0]), "+f"(c[1]), "+f"(c[2]), "+f"(c[3])
                 : "r"(a[0]), "r"(a[1]), "r"(a[2]), "r"(a[3]), "r"(b0), "r"(b1));
}

// ---------------- K1: weight prep ----------------
__global__ void prep_kernel(const float* __restrict__ Wx, const float* __restrict__ bx,
                            const float* __restrict__ Wfx, const float* __restrict__ bfx,
                            const float* __restrict__ Wsl, const float* __restrict__ bsl,
                            const float* __restrict__ temp) {
    int idx = blockIdx.x * blockDim.x + threadIdx.x;
    if (idx < 256 * 512) {
        int k = idx >> 9, j = idx & 511;
        g_Wb[k * 1024 + j]       = __float2half(Wx[idx]);
        g_Wb[k * 1024 + 512 + j] = __float2half(Wfx[idx]);
    }
    if (idx < 512) { g_bias[idx] = bx[idx]; g_bias[512 + idx] = bfx[idx]; }
    if (idx < 4096) g_Wsb[idx] = __float2half(Wsl[idx]);
    if (idx < 64)   g_bslice[idx] = bsl[idx];
    if (idx < 8) {
        float t = temp[idx];
        t = fminf(fmaxf(t, 0.5f), 5.0f);
        g_invtemp[idx] = 1.0f / t;
    }
}

// ---------------- K2: PF = X @ [Wx|Wfx] + bias  (fp16 out) ----------------
// Block: 128 rows x all 1024 cols (8 chunks of 128). 512 threads = 16 warps (4x4),
// warp tile 32x32. Full K=256 A-tile resident in smem (X read once from DRAM).
static constexpr int ASTR = 264;  // 256 + 8 pad (conflict-free ldmatrix)
static constexpr int BSTR = 136;  // 128 + 8 pad
static constexpr int K2_SMEM = 128 * ASTR * 2 + 256 * BSTR * 2;  // 137216 B

__global__ void __launch_bounds__(512) gemm1_kernel(const float* __restrict__ x) {
    extern __shared__ char smem[];
    __half* As = (__half*)smem;                      // [128][264]
    __half* Bs = (__half*)(smem + 128 * ASTR * 2);   // [256][136]
    const int tid = threadIdx.x, warpid = tid >> 5, lane = tid & 31;
    const int mtile = blockIdx.x;
    const float* xrow = x + (size_t)mtile * 128 * 256;

    // stage A (fp32 -> fp16)
    for (int i = tid; i < 128 * 64; i += 512) {
        int r = i >> 6, c4 = (i & 63) * 4;
        float4 v = *(const float4*)(xrow + r * 256 + c4);
        __half2* dst = (__half2*)(As + r * ASTR + c4);
        dst[0] = __floats2half2_rn(v.x, v.y);
        dst[1] = __floats2half2_rn(v.z, v.w);
    }

    const int wm = warpid >> 2, wn = warpid & 3;
    for (int chunk = 0; chunk < 8; chunk++) {
        const int nbase = chunk * 128;
        __syncthreads();  // protect Bs (prev readers) + As first time
        for (int i = tid; i < 256 * 16; i += 512) {
            int k = i >> 4, c8 = (i & 15) * 8;
            *(uint4*)(Bs + k * BSTR + c8) = *(const uint4*)(g_Wb + k * 1024 + nbase + c8);
        }
        __syncthreads();

        float acc[2][4][4];
        #pragma unroll
        for (int mi = 0; mi < 2; mi++)
            #pragma unroll
            for (int ni = 0; ni < 4; ni++)
                #pragma unroll
                for (int q = 0; q < 4; q++) acc[mi][ni][q] = 0.f;

        #pragma unroll
        for (int kk = 0; kk < 256; kk += 16) {
            uint32_t a[2][4], bfr[2][4];
            #pragma unroll
            for (int mi = 0; mi < 2; mi++) {
                int row = wm * 32 + mi * 16 + (lane & 15);
                int col = kk + (lane >> 4) * 8;
                ldm_x4(a[mi], smem_u32(As + row * ASTR + col));
            }
            #pragma unroll
            for (int p = 0; p < 2; p++) {
                int krow = kk + (lane & 15);
                int col = wn * 32 + p * 16 + (lane >> 4) * 8;
                ldm_x4_t(bfr[p], smem_u32(Bs + krow * BSTR + col));
            }
            #pragma unroll
            for (int mi = 0; mi < 2; mi++)
                #pragma unroll
                for (int ni = 0; ni < 4; ni++)
                    mma_f16(acc[mi][ni], a[mi], bfr[ni >> 1][(ni & 1) * 2], bfr[ni >> 1][(ni & 1) * 2 + 1]);
        }

        // epilogue: + bias, fp16, store
        #pragma unroll
        for (int mi = 0; mi < 2; mi++) {
            int r0 = mtile * 128 + wm * 32 + mi * 16 + (lane >> 2);
            #pragma unroll
            for (int ni = 0; ni < 4; ni++) {
                int col = nbase + wn * 32 + ni * 8 + (lane & 3) * 2;
                float b0 = g_bias[col], b1 = g_bias[col + 1];
                *(__half2*)(g_PF + (size_t)r0 * 1024 + col) =
                    __floats2half2_rn(acc[mi][ni][0] + b0, acc[mi][ni][1] + b1);
                *(__half2*)(g_PF + (size_t)(r0 + 8) * 1024 + col) =
                    __floats2half2_rn(acc[mi][ni][2] + b0, acc[mi][ni][3] + b1);
            }
        }
    }
}

// ---------------- K3: logits -> softmax -> weighted aggregation ----------------
// Grid (64 splits, 16 bh). Block: 256 threads (8 warps), 16 tiles of 64 tokens.
// smem layout (bytes):
static constexpr int OFF_PS  = 0;
static constexpr int OFF_FS  = OFF_PS + 64 * 72 * 2;
static constexpr int OFF_WSS = OFF_FS + 64 * 72 * 2;
static constexpr int OFF_WGT = OFF_WSS + 64 * 72 * 2;
static constexpr int OFF_LG  = OFF_WGT + 64 * 72 * 2;      // float [64][68]
static constexpr int OFF_NRM = OFF_LG + 64 * 68 * 4;       // float [64]
static constexpr int OFF_BSL = OFF_NRM + 64 * 4;           // float [64]
static constexpr int K3_SMEM = OFF_BSL + 64 * 4;           // 54784

__global__ void __launch_bounds__(256) stage2_kernel() {
    extern __shared__ char smem[];
    __half* Ps  = (__half*)(smem + OFF_PS);
    __half* Fs  = (__half*)(smem + OFF_FS);
    __half* Wss = (__half*)(smem + OFF_WSS);
    __half* Wgt = (__half*)(smem + OFF_WGT);
    float* Lg  = (float*)(smem + OFF_LG);
    float* nrm = (float*)(smem + OFF_NRM);
    float* bsl = (float*)(smem + OFF_BSL);

    const int tid = threadIdx.x, warpid = tid >> 5, lane = tid & 31;
    const int split = blockIdx.x, bh = blockIdx.y;
    const int b = bh >> 3, h = bh & 7;
    const int wq = warpid >> 2;   // 0..1
    const int wr = warpid & 3;    // 0..3

    // preload W_slice, bias, zero norm
    for (int i = tid; i < 64 * 8; i += 256) {
        int r = i >> 3, c8 = (i & 7) * 8;
        *(uint4*)(Wss + r * 72 + c8) = *(const uint4*)(g_Wsb + r * 64 + c8);
    }
    if (tid < 64) { bsl[tid] = g_bslice[tid]; nrm[tid] = 0.f; }
    const float invt = g_invtemp[h];

    float acc[2][2][4] = {};  // persistent aggregation accumulators (s x d)
    const size_t rowbase = (size_t)(b * NN + split * TOK_PER_SPLIT);
    __syncthreads();

    for (int tile = 0; tile < TILES; tile++) {
        const size_t r0 = rowbase + tile * 64;
        // stage p/f tiles
        for (int i = tid; i < 512; i += 256) {
            int r = i >> 3, c8 = (i & 7) * 8;
            const __half* src = g_PF + (r0 + r) * 1024;
            *(uint4*)(Ps + r * 72 + c8) = *(const uint4*)(src + h * 64 + c8);
            *(uint4*)(Fs + r * 72 + c8) = *(const uint4*)(src + 512 + h * 64 + c8);
        }
        __syncthreads();

        // logits = p @ W_slice : m=token(wq*32), n=s(wr*16), k=d
        {
            float lc[2][2][4] = {};
            #pragma unroll
            for (int kk = 0; kk < 64; kk += 16) {
                uint32_t a[2][4], bb[4];
                #pragma unroll
                for (int mi = 0; mi < 2; mi++) {
                    int row = wq * 32 + mi * 16 + (lane & 15);
                    int col = kk + (lane >> 4) * 8;
                    ldm_x4(a[mi], smem_u32(Ps + row * 72 + col));
                }
                ldm_x4_t(bb, smem_u32(Wss + (kk + (lane & 15)) * 72 + wr * 16 + (lane >> 4) * 8));
                #pragma unroll
                for (int mi = 0; mi < 2; mi++)
                    #pragma unroll
                    for (int ni = 0; ni < 2; ni++)
                        mma_f16(lc[mi][ni], a[mi], bb[ni * 2], bb[ni * 2 + 1]);
            }
            #pragma unroll
            for (int mi = 0; mi < 2; mi++) {
                int t = wq * 32 + mi * 16 + (lane >> 2);
                #pragma unroll
                for (int ni = 0; ni < 2; ni++) {
                    int s0 = wr * 16 + ni * 8 + (lane & 3) * 2;
                    Lg[t * 68 + s0]           = (lc[mi][ni][0] + bsl[s0]) * invt;
                    Lg[t * 68 + s0 + 1]       = (lc[mi][ni][1] + bsl[s0 + 1]) * invt;
                    Lg[(t + 8) * 68 + s0]     = (lc[mi][ni][2] + bsl[s0]) * invt;
                    Lg[(t + 8) * 68 + s0 + 1] = (lc[mi][ni][3] + bsl[s0 + 1]) * invt;
                }
            }
        }
        __syncthreads();

        // softmax: warp handles 8 rows; lane covers 2 columns
        {
            float n0 = 0.f, n1 = 0.f;
            #pragma unroll
            for (int r = 0; r < 8; r++) {
                int t = warpid * 8 + r;
                float v0 = Lg[t * 68 + lane * 2], v1 = Lg[t * 68 + lane * 2 + 1];
                float mx = fmaxf(v0, v1);
                #pragma unroll
                for (int off = 16; off > 0; off >>= 1)
                    mx = fmaxf(mx, __shfl_xor_sync(0xffffffffu, mx, off));
                float e0 = __expf(v0 - mx), e1 = __expf(v1 - mx);
                float sm = e0 + e1;
                #pragma unroll
                for (int off = 16; off > 0; off >>= 1)
                    sm += __shfl_xor_sync(0xffffffffu, sm, off);
                float inv = 1.f / sm;
                float w0 = e0 * inv, w1 = e1 * inv;
                *(__half2*)(Wgt + t * 72 + lane * 2) = __floats2half2_rn(w0, w1);
                n0 += w0; n1 += w1;
            }
            atomicAdd(&nrm[lane * 2], n0);
            atomicAdd(&nrm[lane * 2 + 1], n1);
        }
        __syncthreads();

        // aggregation: out[s,d] += sum_t w[t,s]*f[t,d]; m=s(wq*32), n=d(wr*16), k=t
        #pragma unroll
        for (int kk = 0; kk < 64; kk += 16) {
            uint32_t a[2][4], bb[4];
            #pragma unroll
            for (int mi = 0; mi < 2; mi++) {
                int trow = kk + (lane & 7) + ((lane >> 4) << 3);
                int scol = wq * 32 + mi * 16 + (((lane >> 3) & 1) << 3);
                ldm_x4_t(a[mi], smem_u32(Wgt + trow * 72 + scol));
            }
            ldm_x4_t(bb, smem_u32(Fs + (kk + (lane & 15)) * 72 + wr * 16 + (lane >> 4) * 8));
            #pragma unroll
            for (int mi = 0; mi < 2; mi++)
                #pragma unroll
                for (int ni = 0; ni < 2; ni++)
                    mma_f16(acc[mi][ni], a[mi], bb[ni * 2], bb[ni * 2 + 1]);
        }
        __syncthreads();
    }

    // write per-block partials
    float* pt = g_PartT + ((size_t)(bh * SPLITS + split)) * 4096;
    #pragma unroll
    for (int mi = 0; mi < 2; mi++) {
        int s0 = wq * 32 + mi * 16 + (lane >> 2);
        #pragma unroll
        for (int ni = 0; ni < 2; ni++) {
            int d0 = wr * 16 + ni * 8 + (lane & 3) * 2;
            pt[s0 * 64 + d0]           = acc[mi][ni][0];
            pt[s0 * 64 + d0 + 1]       = acc[mi][ni][1];
            pt[(s0 + 8) * 64 + d0]     = acc[mi][ni][2];
            pt[(s0 + 8) * 64 + d0 + 1] = acc[mi][ni][3];
        }
    }
    if (tid < 64) g_PartN[(bh * SPLITS + split) * 64 + tid] = nrm[tid];
}

// ---------------- K4: reduce partials + normalize ----------------
__global__ void __launch_bounds__(256) reduce_kernel(float* __restrict__ out) {
    const int bid = blockIdx.x;           // 256 blocks
    const int bh = bid >> 4, sc = bid & 15;
    __shared__ float invn[4];
    const int tid = threadIdx.x;
    if (tid < 4) {
        int s = sc * 4 + tid;
        float sum = 0.f;
        #pragma unroll 8
        for (int sp = 0; sp < SPLITS; sp++) sum += g_PartN[(bh * SPLITS + sp) * 64 + s];
        invn[tid] = 1.f / (sum + 0.01f);
    }
    __syncthreads();
    const int sl = tid >> 6, d = tid & 63;
    const int s = sc * 4 + sl;
    float sum = 0.f;
    #pragma unroll 8
    for (int sp = 0; sp < SPLITS; sp++)
        sum += g_PartT[((size_t)(bh * SPLITS + sp)) * 4096 + s * 64 + d];
    out[bh * 4096 + s * 64 + d] = sum * invn[sl];
}

// ---------------- launch ----------------
extern "C" void kernel_launch(void* const* d_in, const int* in_sizes, int n_in,
                              void* d_out, int out_size) {
    const float* x    = (const float*)d_in[0];
    const float* Wx   = (const float*)d_in[1];
    const float* bx   = (const float*)d_in[2];
    const float* Wfx  = (const float*)d_in[3];
    const float* bfx  = (const float*)d_in[4];
    const float* Wsl  = (const float*)d_in[5];
    const float* bsl  = (const float*)d_in[6];
    const float* temp = (const float*)d_in[7];

    cudaFuncSetAttribute(gemm1_kernel, cudaFuncAttributeMaxDynamicSharedMemorySize, K2_SMEM);
    cudaFuncSetAttribute(stage2_kernel, cudaFuncAttributeMaxDynamicSharedMemorySize, K3_SMEM);

    prep_kernel<<<512, 256>>>(Wx, bx, Wfx, bfx, Wsl, bsl, temp);
    gemm1_kernel<<<MROWS / 128, 512, K2_SMEM>>>(x);
    dim3 g3(SPLITS, 16);
    stage2_kernel<<<g3, 256, K3_SMEM>>>();
    reduce_kernel<<<256, 256>>>((float*)d_out);
}

// round 6
// speedup vs baseline: 1.1120x; 1.1120x over previous
#include <cuda_runtime.h>
#include <cuda_fp16.h>
#include <cstdint>
#include <cstddef>

// Problem constants
static constexpr int NN = 65536;
static constexpr int MROWS = 2 * NN;     // 131072 token rows total
static constexpr int NBLK = MROWS / 128; // 1024 fused blocks

// ---------------- device scratch (no allocation allowed) ----------------
__device__ __half g_Wb[256 * 1024];        // [k][h*128 + (0..63 Wx_h | 64..127 Wfx_h)]
__device__ float  g_bias[1024];            // head-major to match
__device__ __half g_Wsb[64 * 64];          // W_slice [d][s]
__device__ float  g_bslice[64];
__device__ float  g_invtemp[8];
__device__ __half g_Part[(size_t)NBLK * 8 * 4096]; // 64 MB fp16 partials
__device__ float  g_PartN[NBLK * 8 * 64];          // 2 MB norm partials

// ---------------- mma helpers ----------------
__device__ __forceinline__ uint32_t smem_u32(const void* p) {
    return (uint32_t)__cvta_generic_to_shared(p);
}
__device__ __forceinline__ void ldm_x4(uint32_t* r, uint32_t addr) {
    asm volatile("ldmatrix.sync.aligned.m8n8.x4.shared.b16 {%0,%1,%2,%3}, [%4];"
                 : "=r"(r[0]), "=r"(r[1]), "=r"(r[2]), "=r"(r[3]) : "r"(addr));
}
__device__ __forceinline__ void ldm_x4_t(uint32_t* r, uint32_t addr) {
    asm volatile("ldmatrix.sync.aligned.m8n8.x4.trans.shared.b16 {%0,%1,%2,%3}, [%4];"
                 : "=r"(r[0]), "=r"(r[1]), "=r"(r[2]), "=r"(r[3]) : "r"(addr));
}
__device__ __forceinline__ void mma_f16(float* c, const uint32_t* a, uint32_t b0, uint32_t b1) {
    asm volatile("mma.sync.aligned.m16n8k16.row.col.f32.f16.f16.f32 "
                 "{%0,%1,%2,%3}, {%4,%5,%6,%7}, {%8,%9}, {%0,%1,%2,%3};"
                 : "+f"(c[0]), "+f"(c[1]), "+f"(c[2]), "+f"(c[3])
                 : "r"(a[0]), "r"(a[1]), "r"(a[2]), "r"(a[3]), "r"(b0), "r"(b1));
}

// ---------------- K1: weight prep (head-major rearrange) ----------------
__global__ void prep_kernel(const float* __restrict__ Wx, const float* __restrict__ bx,
                            const float* __restrict__ Wfx, const float* __restrict__ bfx,
                            const float* __restrict__ Wsl, const float* __restrict__ bsl,
                            const float* __restrict__ temp) {
    int idx = blockIdx.x * blockDim.x + threadIdx.x;
    if (idx < 256 * 512) {
        int k = idx >> 9, j = idx & 511;
        int h = j >> 6, d = j & 63;
        g_Wb[k * 1024 + h * 128 + d]      = __float2half(Wx[idx]);
        g_Wb[k * 1024 + h * 128 + 64 + d] = __float2half(Wfx[idx]);
    }
    if (idx < 512) {
        int h = idx >> 6, d = idx & 63;
        g_bias[h * 128 + d]      = bx[idx];
        g_bias[h * 128 + 64 + d] = bfx[idx];
    }
    if (idx < 4096) g_Wsb[idx] = __float2half(Wsl[idx]);
    if (idx < 64)   g_bslice[idx] = bsl[idx];
    if (idx < 8) {
        float t = temp[idx];
        t = fminf(fmaxf(t, 0.5f), 5.0f);
        g_invtemp[idx] = 1.0f / t;
    }
}

// ---------------- fused kernel ----------------
// 1024 blocks x 512 threads. Block = 128 token rows. Per head:
//   GEMM (128x128, K=256) -> P|F in smem -> logits -> reg softmax -> agg mma
// Emits fp16 (s x d) partials + fp32 norm partials per (block, head).
static constexpr int ASTR = 264, BSTR = 136, PFSTR = 136, WGSTR = 72, WSSTR = 72;
static constexpr int OFF_AS  = 0;
static constexpr int OFF_BS  = OFF_AS + 128 * ASTR * 2;    // 67584
static constexpr int OFF_PFS = OFF_BS + 256 * BSTR * 2;    // +69632
static constexpr int OFF_WGT = OFF_PFS + 128 * PFSTR * 2;  // +34816
static constexpr int OFF_WSS = OFF_WGT + 128 * WGSTR * 2;  // +18432
static constexpr int OFF_NRM = OFF_WSS + 64 * WSSTR * 2;   // +9216
static constexpr int FUSED_SMEM = OFF_NRM + 64 * 4;        // 199936 B

__global__ void __launch_bounds__(512) fused_kernel(const float* __restrict__ x) {
    extern __shared__ char smem[];
    __half* As  = (__half*)(smem + OFF_AS);    // [128][264]
    __half* Bs  = (__half*)(smem + OFF_BS);    // [256][136]
    __half* PFs = (__half*)(smem + OFF_PFS);   // [128][136] p: cols 0-63, f: 64-127
    __half* Wgt = (__half*)(smem + OFF_WGT);   // [128][72]
    __half* Wss = (__half*)(smem + OFF_WSS);   // [64][72]
    float*  nrm = (float*)(smem + OFF_NRM);    // [64]

    const int tid = threadIdx.x, warpid = tid >> 5, lane = tid & 31;
    const int blk = blockIdx.x;
    const float* xrow = x + (size_t)blk * 128 * 256;

    // stage X tile (fp32 -> fp16)
    for (int i = tid; i < 128 * 64; i += 512) {
        int r = i >> 6, c4 = (i & 63) * 4;
        float4 v = *(const float4*)(xrow + r * 256 + c4);
        __half2* dst = (__half2*)(As + r * ASTR + c4);
        dst[0] = __floats2half2_rn(v.x, v.y);
        dst[1] = __floats2half2_rn(v.z, v.w);
    }
    // stage W_slice
    for (int i = tid; i < 64 * 8; i += 512) {
        int r = i >> 3, c8 = (i & 7) * 8;
        *(uint4*)(Wss + r * WSSTR + c8) = *(const uint4*)(g_Wsb + r * 64 + c8);
    }
    // per-thread slice-bias registers (cols fixed per thread) for logits warps
    float bslr[8][2];
    if (warpid < 8) {
        #pragma unroll
        for (int ni = 0; ni < 8; ni++) {
            int c = ni * 8 + (lane & 3) * 2;
            bslr[ni][0] = g_bslice[c];
            bslr[ni][1] = g_bslice[c + 1];
        }
    }

    const int wm = warpid >> 2, wn = warpid & 3;     // GEMM 4x4 warp grid
    const int sbase = (warpid >> 2) * 16;            // agg s-tile
    const int dbase = (warpid & 3) * 16;             // agg d-tile

    for (int h = 0; h < 8; h++) {
        const float invt = g_invtemp[h];
        // ---- stage this head's weight chunk [256][128] ----
        for (int i = tid; i < 256 * 16; i += 512) {
            int k = i >> 4, c8 = (i & 15) * 8;
            *(uint4*)(Bs + k * BSTR + c8) = *(const uint4*)(g_Wb + k * 1024 + h * 128 + c8);
        }
        __syncthreads();

        // ---- GEMM: [128 tok] x [128 cols(p|f)], K=256 ----
        float acc[2][4][4];
        #pragma unroll
        for (int mi = 0; mi < 2; mi++)
            #pragma unroll
            for (int ni = 0; ni < 4; ni++)
                #pragma unroll
                for (int q = 0; q < 4; q++) acc[mi][ni][q] = 0.f;

        #pragma unroll
        for (int kk = 0; kk < 256; kk += 16) {
            uint32_t a[2][4], bfr[2][4];
            #pragma unroll
            for (int mi = 0; mi < 2; mi++) {
                int row = wm * 32 + mi * 16 + (lane & 15);
                int col = kk + (lane >> 4) * 8;
                ldm_x4(a[mi], smem_u32(As + row * ASTR + col));
            }
            #pragma unroll
            for (int p = 0; p < 2; p++) {
                int krow = kk + (lane & 15);
                int col = wn * 32 + p * 16 + (lane >> 4) * 8;
                ldm_x4_t(bfr[p], smem_u32(Bs + krow * BSTR + col));
            }
            #pragma unroll
            for (int mi = 0; mi < 2; mi++)
                #pragma unroll
                for (int ni = 0; ni < 4; ni++)
                    mma_f16(acc[mi][ni], a[mi], bfr[ni >> 1][(ni & 1) * 2], bfr[ni >> 1][(ni & 1) * 2 + 1]);
        }

        // ---- epilogue: +bias -> fp16 smem (p|f) ----
        #pragma unroll
        for (int mi = 0; mi < 2; mi++) {
            int r0 = wm * 32 + mi * 16 + (lane >> 2);
            #pragma unroll
            for (int ni = 0; ni < 4; ni++) {
                int col = wn * 32 + ni * 8 + (lane & 3) * 2;
                float b0 = g_bias[h * 128 + col], b1 = g_bias[h * 128 + col + 1];
                *(__half2*)(PFs + r0 * PFSTR + col) =
                    __floats2half2_rn(acc[mi][ni][0] + b0, acc[mi][ni][1] + b1);
                *(__half2*)(PFs + (r0 + 8) * PFSTR + col) =
                    __floats2half2_rn(acc[mi][ni][2] + b0, acc[mi][ni][3] + b1);
            }
        }
        if (tid < 64) nrm[tid] = 0.f;
        __syncthreads();

        // ---- logits + softmax: warps 0..7, each 16 tokens x 64 slices ----
        if (warpid < 8) {
            const int tb = warpid * 16;
            float lc[8][4];
            #pragma unroll
            for (int f = 0; f < 8; f++)
                #pragma unroll
                for (int q = 0; q < 4; q++) lc[f][q] = 0.f;

            #pragma unroll
            for (int kk = 0; kk < 64; kk += 16) {
                uint32_t a[4];
                ldm_x4(a, smem_u32(PFs + (tb + (lane & 15)) * PFSTR + kk + (lane >> 4) * 8));
                #pragma unroll
                for (int ng = 0; ng < 4; ng++) {
                    uint32_t bb[4];
                    ldm_x4_t(bb, smem_u32(Wss + (kk + (lane & 15)) * WSSTR + ng * 16 + (lane >> 4) * 8));
                    mma_f16(lc[ng * 2], a, bb[0], bb[1]);
                    mma_f16(lc[ng * 2 + 1], a, bb[2], bb[3]);
                }
            }
            // bias + temp, row max over 64 (16 local + shfl over lane&3 group)
            float mA = -1e30f, mB = -1e30f;
            #pragma unroll
            for (int f = 0; f < 8; f++) {
                lc[f][0] = (lc[f][0] + bslr[f][0]) * invt;
                lc[f][1] = (lc[f][1] + bslr[f][1]) * invt;
                lc[f][2] = (lc[f][2] + bslr[f][0]) * invt;
                lc[f][3] = (lc[f][3] + bslr[f][1]) * invt;
                mA = fmaxf(mA, fmaxf(lc[f][0], lc[f][1]));
                mB = fmaxf(mB, fmaxf(lc[f][2], lc[f][3]));
            }
            #pragma unroll
            for (int off = 1; off <= 2; off <<= 1) {
                mA = fmaxf(mA, __shfl_xor_sync(0xffffffffu, mA, off));
                mB = fmaxf(mB, __shfl_xor_sync(0xffffffffu, mB, off));
            }
            float sA = 0.f, sB = 0.f;
            #pragma unroll
            for (int f = 0; f < 8; f++) {
                lc[f][0] = __expf(lc[f][0] - mA);
                lc[f][1] = __expf(lc[f][1] - mA);
                lc[f][2] = __expf(lc[f][2] - mB);
                lc[f][3] = __expf(lc[f][3] - mB);
                sA += lc[f][0] + lc[f][1];
                sB += lc[f][2] + lc[f][3];
            }
            #pragma unroll
            for (int off = 1; off <= 2; off <<= 1) {
                sA += __shfl_xor_sync(0xffffffffu, sA, off);
                sB += __shfl_xor_sync(0xffffffffu, sB, off);
            }
            const float iA = 1.f / sA, iB = 1.f / sB;
            const int rA = tb + (lane >> 2);
            float ncol[8][2];
            #pragma unroll
            for (int f = 0; f < 8; f++) {
                float w0 = lc[f][0] * iA, w1 = lc[f][1] * iA;
                float w2 = lc[f][2] * iB, w3 = lc[f][3] * iB;
                int c = f * 8 + (lane & 3) * 2;
                *(__half2*)(Wgt + rA * WGSTR + c)       = __floats2half2_rn(w0, w1);
                *(__half2*)(Wgt + (rA + 8) * WGSTR + c) = __floats2half2_rn(w2, w3);
                ncol[f][0] = w0 + w2;
                ncol[f][1] = w1 + w3;
            }
            // reduce ncol over the 8 lanes sharing a column set (lane>>2 varies)
            #pragma unroll
            for (int f = 0; f < 8; f++) {
                #pragma unroll
                for (int off = 4; off <= 16; off <<= 1) {
                    ncol[f][0] += __shfl_xor_sync(0xffffffffu, ncol[f][0], off);
                    ncol[f][1] += __shfl_xor_sync(0xffffffffu, ncol[f][1], off);
                }
            }
            if (lane < 4) {
                #pragma unroll
                for (int f = 0; f < 8; f++) {
                    int c = f * 8 + lane * 2;
                    atomicAdd(&nrm[c], ncol[f][0]);
                    atomicAdd(&nrm[c + 1], ncol[f][1]);
                }
            }
        }
        __syncthreads();

        // ---- aggregation: out[s,d] = sum_t w[t,s] * f[t,d], all 16 warps ----
        float ag[2][4];
        #pragma unroll
        for (int ng = 0; ng < 2; ng++)
            #pragma unroll
            for (int q = 0; q < 4; q++) ag[ng][q] = 0.f;

        #pragma unroll
        for (int kk = 0; kk < 128; kk += 16) {
            uint32_t a[4], bb[4];
            int trow = kk + (lane & 7) + ((lane >> 4) << 3);
            int scol = sbase + (((lane >> 3) & 1) << 3);
            ldm_x4_t(a, smem_u32(Wgt + trow * WGSTR + scol));
            ldm_x4_t(bb, smem_u32(PFs + (kk + (lane & 15)) * PFSTR + 64 + dbase + (lane >> 4) * 8));
            mma_f16(ag[0], a, bb[0], bb[1]);
            mma_f16(ag[1], a, bb[2], bb[3]);
        }
        __half* pt = g_Part + ((size_t)(blk * 8 + h)) * 4096;
        #pragma unroll
        for (int ng = 0; ng < 2; ng++) {
            int s = sbase + (lane >> 2);
            int d = dbase + ng * 8 + (lane & 3) * 2;
            *(__half2*)(pt + s * 64 + d)       = __floats2half2_rn(ag[ng][0], ag[ng][1]);
            *(__half2*)(pt + (s + 8) * 64 + d) = __floats2half2_rn(ag[ng][2], ag[ng][3]);
        }
        if (tid < 64) g_PartN[(blk * 8 + h) * 64 + tid] = nrm[tid];
        __syncthreads();
    }
}

// ---------------- reduce: sum 512 block-partials per (b,h), normalize ----------------
__global__ void __launch_bounds__(256) reduce_kernel(float* __restrict__ out) {
    const int bid = blockIdx.x;         // 256 blocks: bh x 16 s-chunks
    const int bh = bid >> 4, sc = bid & 15;
    const int b = bh >> 3, h = bh & 7;
    __shared__ float invn[4];
    const int tid = threadIdx.x, warpid = tid >> 5, lane = tid & 31;

    if (warpid < 4) {
        int s = sc * 4 + warpid;
        float p = 0.f;
        for (int i = lane; i < 512; i += 32)
            p += g_PartN[((b * 512 + i) * 8 + h) * 64 + s];
        #pragma unroll
        for (int off = 16; off > 0; off >>= 1)
            p += __shfl_xor_sync(0xffffffffu, p, off);
        if (lane == 0) invn[warpid] = 1.f / (p + 0.01f);
    }
    __syncthreads();

    const int sl = tid >> 6, d = tid & 63;
    const int s = sc * 4 + sl;
    float sum = 0.f;
    #pragma unroll 8
    for (int i = 0; i < 512; i++)
        sum += __half2float(g_Part[((size_t)((b * 512 + i) * 8 + h)) * 4096 + s * 64 + d]);
    out[bh * 4096 + s * 64 + d] = sum * invn[sl];
}

// 4th launch so ncu's "-s 5 -c 1" lands on fused_kernel (launch idx 5 = replay-2 fused)
__global__ void nop_kernel() {}

// ---------------- launch ----------------
extern "C" void kernel_launch(void* const* d_in, const int* in_sizes, int n_in,
                              void* d_out, int out_size) {
    const float* x    = (const float*)d_in[0];
    const float* Wx   = (const float*)d_in[1];
    const float* bx   = (const float*)d_in[2];
    const float* Wfx  = (const float*)d_in[3];
    const float* bfx  = (const float*)d_in[4];
    const float* Wsl  = (const float*)d_in[5];
    const float* bsl  = (const float*)d_in[6];
    const float* temp = (const float*)d_in[7];

    cudaFuncSetAttribute(fused_kernel, cudaFuncAttributeMaxDynamicSharedMemorySize, FUSED_SMEM);

    prep_kernel<<<512, 256>>>(Wx, bx, Wfx, bfx, Wsl, bsl, temp);
    fused_kernel<<<NBLK, 512, FUSED_SMEM>>>(x);
    reduce_kernel<<<256, 256>>>((float*)d_out);
    nop_kernel<<<1, 32>>>();
}